// round 4
// baseline (speedup 1.0000x reference)
#include <cuda_runtime.h>
#include <cstdint>

#define DIMK 2048
#define NEXP 64
#define BM   128
#define KC   32
#define NCH  (DIMK / KC)        // 64
#define APAD 36
#define BPAD 36
#define NT   128
#define DELTA 3e-4f

// stage layout (words): A_hi[128][36] | A_lo | B_hi[64][36] | B_lo
#define A_WORDS (BM * APAD)             // 4608
#define B_WORDS (NEXP * BPAD)           // 2304
#define OFF_AH  0
#define OFF_AL  (A_WORDS)
#define OFF_BH  (2 * A_WORDS)
#define OFF_BL  (2 * A_WORDS + B_WORDS)
#define STAGE_WORDS (2 * A_WORDS + 2 * B_WORDS)   // 13824
#define SMEM_BYTES (2 * STAGE_WORDS * 4)          // 110592

__device__ int g_cnt;
__device__ int g_list[40960];

// ---------- helpers ----------
__device__ __forceinline__ uint32_t smem_u32(const void* p) {
    uint32_t a;
    asm("{ .reg .u64 t; cvta.to.shared.u64 t, %1; cvt.u32.u64 %0, t; }" : "=r"(a) : "l"(p));
    return a;
}
__device__ __forceinline__ void split_tf32(float v, uint32_t& h, uint32_t& l) {
    uint32_t hv;
    asm("cvt.rna.tf32.f32 %0, %1;" : "=r"(hv) : "f"(v));
    h = hv;
    l = __float_as_uint(v - __uint_as_float(hv));
}
__device__ __forceinline__ void sts128(uint32_t a, uint32_t x, uint32_t y, uint32_t z, uint32_t w) {
    asm volatile("st.shared.v4.b32 [%0], {%1,%2,%3,%4};" :: "r"(a), "r"(x), "r"(y), "r"(z), "r"(w) : "memory");
}
__device__ __forceinline__ void ldm4(uint32_t addr, uint32_t* r) {
    asm volatile("ldmatrix.sync.aligned.m8n8.x4.shared.b16 {%0,%1,%2,%3}, [%4];"
                 : "=r"(r[0]), "=r"(r[1]), "=r"(r[2]), "=r"(r[3]) : "r"(addr));
}
__device__ __forceinline__ void mma8(float* c, const uint32_t* a, uint32_t b0, uint32_t b1) {
    asm volatile(
        "mma.sync.aligned.m16n8k8.row.col.f32.tf32.tf32.f32 "
        "{%0,%1,%2,%3}, {%4,%5,%6,%7}, {%8,%9}, {%0,%1,%2,%3};"
        : "+f"(c[0]), "+f"(c[1]), "+f"(c[2]), "+f"(c[3])
        : "r"(a[0]), "r"(a[1]), "r"(a[2]), "r"(a[3]), "r"(b0), "r"(b1));
}

struct Top3 {
    float v0, v1, v2;
    int   i0, i1;
};
__device__ __forceinline__ void t3_insert(Top3& t, float v, int i) {
    if (v > t.v0 || (v == t.v0 && i < t.i0)) {
        t.v2 = t.v1; t.v1 = t.v0; t.i1 = t.i0; t.v0 = v; t.i0 = i;
    } else if (v > t.v1 || (v == t.v1 && i < t.i1)) {
        t.v2 = t.v1; t.v1 = v; t.i1 = i;
    } else if (v > t.v2) {
        t.v2 = v;
    }
}
__device__ __forceinline__ void t3_merge_xor(Top3& t, int m) {
    float pv0 = __shfl_xor_sync(0xFFFFFFFFu, t.v0, m);
    float pv1 = __shfl_xor_sync(0xFFFFFFFFu, t.v1, m);
    float pv2 = __shfl_xor_sync(0xFFFFFFFFu, t.v2, m);
    int   pi0 = __shfl_xor_sync(0xFFFFFFFFu, t.i0, m);
    int   pi1 = __shfl_xor_sync(0xFFFFFFFFu, t.i1, m);
    t3_insert(t, pv0, pi0);
    t3_insert(t, pv1, pi1);
    t3_insert(t, pv2, 0x40000000);
}

__global__ void zero_cnt_kernel() { g_cnt = 0; }

// =========================================================================
// Main GEMM: emulated-fp32 via 3-pass tf32 mma.sync + top-2 epilogue
// =========================================================================
__global__ __launch_bounds__(NT, 2)
void router_mma(const float* __restrict__ x,
                const float* __restrict__ w,
                float* __restrict__ out_mask,
                float* __restrict__ out_w,
                float* __restrict__ out_i)
{
    extern __shared__ float smf[];
    const uint32_t smb = smem_u32(smf);

    const int tid  = threadIdx.x;
    const int lane = tid & 31;
    const int wid  = tid >> 5;          // 0..3
    const int gr   = lane >> 2;
    const int gc   = lane & 3;
    const int m0   = wid * 32;
    const int mbase = blockIdx.x * BM;

    // -------- global load assignments --------
    const float4* xr = (const float4*)(x + (size_t)(mbase + tid) * DIMK);
    const int brow = tid & 63;
    const int bh   = tid >> 6;          // 0/1 -> k-half of the expert row
    const float4* wr = (const float4*)(w + (size_t)brow * DIMK);

    // -------- accumulators --------
    float acc[2][8][4];
#pragma unroll
    for (int i = 0; i < 2; i++)
#pragma unroll
        for (int j = 0; j < 8; j++)
#pragma unroll
            for (int r = 0; r < 4; r++) acc[i][j][r] = 0.0f;

    // -------- fragment smem addresses (per lane, per stage) --------
    // A ldmatrix (i-tile): lane addr = A + ((m0 + 16i + (mat&1)*8 + lane&7)*APAD + kk + (mat>>1)*4)
    const int amat = lane >> 3;
    const int arow_off = (amat & 1) * 8 + (lane & 7);
    const int acol_off = (amat >> 1) * 4;
    // B ldmatrix (j-pair): lane addr = B + ((jp*16 + (mat>>1)*8 + lane&7)*BPAD + kk + (mat&1)*4)
    const int brow_off = (amat >> 1) * 8 + (lane & 7);
    const int bcol_off = (amat & 1) * 4;

    // prefetch chunk 0
    float4 ax[8], bxv[4];
#pragma unroll
    for (int s = 0; s < 8; s++) ax[s] = xr[s];
#pragma unroll
    for (int j = 0; j < 4; j++) bxv[j] = wr[bh * 4 + j];

#pragma unroll 1
    for (int c = 0; c < NCH; c++) {
        const uint32_t st = smb + (uint32_t)((c & 1) * STAGE_WORDS * 4);
        if (c >= 2) __syncthreads();

        // ---- split & store A (token row tid) ----
        const uint32_t aH = st + (uint32_t)(OFF_AH + tid * APAD) * 4u;
        const uint32_t aL = st + (uint32_t)(OFF_AL + tid * APAD) * 4u;
#pragma unroll
        for (int s = 0; s < 8; s++) {
            uint32_t hx, lx, hy, ly, hz, lz, hw, lw;
            split_tf32(ax[s].x, hx, lx);
            split_tf32(ax[s].y, hy, ly);
            split_tf32(ax[s].z, hz, lz);
            split_tf32(ax[s].w, hw, lw);
            sts128(aH + s * 16u, hx, hy, hz, hw);
            sts128(aL + s * 16u, lx, ly, lz, lw);
        }
        // ---- split & store B (expert row brow, k-half bh) ----
        const uint32_t bHc = st + (uint32_t)(OFF_BH + brow * BPAD + bh * 16) * 4u;
        const uint32_t bLc = st + (uint32_t)(OFF_BL + brow * BPAD + bh * 16) * 4u;
#pragma unroll
        for (int j = 0; j < 4; j++) {
            uint32_t hx, lx, hy, ly, hz, lz, hw, lw;
            split_tf32(bxv[j].x, hx, lx);
            split_tf32(bxv[j].y, hy, ly);
            split_tf32(bxv[j].z, hz, lz);
            split_tf32(bxv[j].w, hw, lw);
            sts128(bHc + j * 16u, hx, hy, hz, hw);
            sts128(bLc + j * 16u, lx, ly, lz, lw);
        }

        // ---- prefetch next chunk ----
        if (c + 1 < NCH) {
#pragma unroll
            for (int s = 0; s < 8; s++) ax[s] = xr[(c + 1) * 8 + s];
#pragma unroll
            for (int j = 0; j < 4; j++) bxv[j] = wr[(c + 1) * 8 + bh * 4 + j];
        }
        __syncthreads();

        // ---- compute: 4 k8-steps, 3 passes each ----
#pragma unroll
        for (int kq = 0; kq < 4; kq++) {
            const int kk = kq * 8;
            uint32_t ah[2][4], al[2][4];
#pragma unroll
            for (int i = 0; i < 2; i++) {
                uint32_t arow = (uint32_t)(m0 + 16 * i + arow_off);
                uint32_t aoff = (arow * APAD + kk + acol_off) * 4u;
                ldm4(st + OFF_AH * 4u + aoff, ah[i]);
                ldm4(st + OFF_AL * 4u + aoff, al[i]);
            }
            uint32_t bhf[8][2], blf[8][2];
#pragma unroll
            for (int jp = 0; jp < 4; jp++) {
                uint32_t nrow = (uint32_t)(jp * 16 + brow_off);
                uint32_t boff = (nrow * BPAD + kk + bcol_off) * 4u;
                uint32_t t4[4];
                ldm4(st + OFF_BH * 4u + boff, t4);
                bhf[2 * jp][0] = t4[0]; bhf[2 * jp][1] = t4[1];
                bhf[2 * jp + 1][0] = t4[2]; bhf[2 * jp + 1][1] = t4[3];
                ldm4(st + OFF_BL * 4u + boff, t4);
                blf[2 * jp][0] = t4[0]; blf[2 * jp][1] = t4[1];
                blf[2 * jp + 1][0] = t4[2]; blf[2 * jp + 1][1] = t4[3];
            }
#pragma unroll
            for (int i = 0; i < 2; i++)
#pragma unroll
                for (int j = 0; j < 8; j++) {
                    mma8(acc[i][j], ah[i], bhf[j][0], bhf[j][1]);   // hi*hi
                    mma8(acc[i][j], ah[i], blf[j][0], blf[j][1]);   // hi*lo
                    mma8(acc[i][j], al[i], bhf[j][0], bhf[j][1]);   // lo*hi
                }
        }
    }

    // =================== epilogue: top-2 per token ===================
#pragma unroll
    for (int i = 0; i < 2; i++) {
#pragma unroll
        for (int rh = 0; rh < 2; rh++) {
            const int m = m0 + 16 * i + 8 * rh + gr;
            Top3 t; t.v0 = -1e30f; t.v1 = -1e30f; t.v2 = -1e30f; t.i0 = 0; t.i1 = 0;
#pragma unroll
            for (int j = 0; j < 8; j++) {
#pragma unroll
                for (int b = 0; b < 2; b++) {
                    t3_insert(t, acc[i][j][rh * 2 + b], 8 * j + 2 * gc + b);
                }
            }
            t3_merge_xor(t, 1);
            t3_merge_xor(t, 2);

            const size_t g = (size_t)(mbase + m);
            if (gc == 0) {
                float e1  = expf(t.v1 - t.v0);
                float inv = 1.0f / (1.0f + e1);
                out_w[g * 2 + 0] = inv;
                out_w[g * 2 + 1] = e1 * inv;
                out_i[g * 2 + 0] = (float)t.i0;
                out_i[g * 2 + 1] = (float)t.i1;
                if ((t.v0 - t.v1 < DELTA) || (t.v1 - t.v2 < DELTA)) {
                    int slot = atomicAdd(&g_cnt, 1);
                    if (slot < 40960) g_list[slot] = (int)g;
                }
            }
            float* mrow = out_mask + g * NEXP + gc * 16;
#pragma unroll
            for (int q = 0; q < 4; q++) {
                int e0 = gc * 16 + q * 4;
                float4 mv;
                mv.x = (e0 + 0 == t.i0 || e0 + 0 == t.i1) ? 1.0f : 0.0f;
                mv.y = (e0 + 1 == t.i0 || e0 + 1 == t.i1) ? 1.0f : 0.0f;
                mv.z = (e0 + 2 == t.i0 || e0 + 2 == t.i1) ? 1.0f : 0.0f;
                mv.w = (e0 + 3 == t.i0 || e0 + 3 == t.i1) ? 1.0f : 0.0f;
                *(float4*)(mrow + q * 4) = mv;
            }
        }
    }
}

// =========================================================================
// Repair: exact fp32 recompute of low-margin tokens (one warp per token)
// =========================================================================
__global__ __launch_bounds__(256)
void repair_kernel(const float* __restrict__ x,
                   const float* __restrict__ w,
                   float* __restrict__ out_mask,
                   float* __restrict__ out_w,
                   float* __restrict__ out_i)
{
    const int lane = threadIdx.x & 31;
    const int wgid = (blockIdx.x * blockDim.x + threadIdx.x) >> 5;
    const int nwarps = (gridDim.x * blockDim.x) >> 5;
    int cnt = g_cnt;
    if (cnt > 40960) cnt = 40960;

    for (int t = wgid; t < cnt; t += nwarps) {
        const int tok = g_list[t];
        const float4* xr = (const float4*)(x + (size_t)tok * DIMK);
        const float4* wa = (const float4*)(w + (size_t)lane * DIMK);
        const float4* wb = (const float4*)(w + (size_t)(lane + 32) * DIMK);

        float4 ma = make_float4(0, 0, 0, 0), mb = make_float4(0, 0, 0, 0);
#pragma unroll 1
        for (int seg = 0; seg < 8; seg++) {
            float4 ca = make_float4(0, 0, 0, 0), cb = make_float4(0, 0, 0, 0);
#pragma unroll 8
            for (int q = 0; q < 64; q++) {
                float4 xv = xr[seg * 64 + q];
                float4 va = wa[seg * 64 + q];
                float4 vb = wb[seg * 64 + q];
                ca.x = fmaf(xv.x, va.x, ca.x); ca.y = fmaf(xv.y, va.y, ca.y);
                ca.z = fmaf(xv.z, va.z, ca.z); ca.w = fmaf(xv.w, va.w, ca.w);
                cb.x = fmaf(xv.x, vb.x, cb.x); cb.y = fmaf(xv.y, vb.y, cb.y);
                cb.z = fmaf(xv.z, vb.z, cb.z); cb.w = fmaf(xv.w, vb.w, cb.w);
            }
            ma.x += ca.x; ma.y += ca.y; ma.z += ca.z; ma.w += ca.w;
            mb.x += cb.x; mb.y += cb.y; mb.z += cb.z; mb.w += cb.w;
        }
        float la = (ma.x + ma.y) + (ma.z + ma.w);
        float lb = (mb.x + mb.y) + (mb.z + mb.w);

        Top3 tp; tp.v0 = -1e30f; tp.v1 = -1e30f; tp.v2 = -1e30f; tp.i0 = 0; tp.i1 = 0;
        t3_insert(tp, la, lane);
        t3_insert(tp, lb, lane + 32);
        t3_merge_xor(tp, 1);
        t3_merge_xor(tp, 2);
        t3_merge_xor(tp, 4);
        t3_merge_xor(tp, 8);
        t3_merge_xor(tp, 16);

        if (lane == 0) {
            float e1  = expf(tp.v1 - tp.v0);
            float inv = 1.0f / (1.0f + e1);
            out_w[(size_t)tok * 2 + 0] = inv;
            out_w[(size_t)tok * 2 + 1] = e1 * inv;
            out_i[(size_t)tok * 2 + 0] = (float)tp.i0;
            out_i[(size_t)tok * 2 + 1] = (float)tp.i1;
        }
        __syncwarp();
        out_mask[(size_t)tok * NEXP + lane] =
            (lane == tp.i0 || lane == tp.i1) ? 1.0f : 0.0f;
        out_mask[(size_t)tok * NEXP + lane + 32] =
            (lane + 32 == tp.i0 || lane + 32 == tp.i1) ? 1.0f : 0.0f;
    }
}

extern "C" void kernel_launch(void* const* d_in, const int* in_sizes, int n_in,
                              void* d_out, int out_size) {
    const float* x = (const float*)d_in[0];   // (N, 2048) fp32
    const float* w = (const float*)d_in[1];   // (64, 2048) fp32
    int n_tokens = in_sizes[0] / DIMK;        // 32768

    float* out      = (float*)d_out;
    float* out_mask = out;                                  // N*64
    float* out_w    = out + (size_t)n_tokens * NEXP;        // N*2
    float* out_i    = out_w + (size_t)n_tokens * 2;         // N*2

    static bool attr_done = false;
    if (!attr_done) {
        cudaFuncSetAttribute(router_mma, cudaFuncAttributeMaxDynamicSharedMemorySize, SMEM_BYTES);
        attr_done = true;
    }

    zero_cnt_kernel<<<1, 1>>>();
    router_mma<<<n_tokens / BM, NT, SMEM_BYTES>>>(x, w, out_mask, out_w, out_i);
    repair_kernel<<<128, 256>>>(x, w, out_mask, out_w, out_i);
}

// round 5
// speedup vs baseline: 1.1239x; 1.1239x over previous
#include <cuda_runtime.h>
#include <cuda_bf16.h>
#include <cstdint>

#define DIMK 2048
#define NEXP 64
#define BM   64              // tokens per CTA
#define NT   128             // threads per CTA (4 warps, warp tile m16 x n64)
#define NCH  (DIMK / 32)     // 64 chunks of k=32
#define DELTA 1e-4f

// stage layout (bytes): bf16 tiles, rows padded to 40 elems (80B) for
// conflict-free ldmatrix (r*20 mod 32 -> distinct bank quads)
#define ROWB    80
#define OFF_AH  0
#define OFF_AL  5120
#define OFF_BH  10240
#define OFF_BL  15360
#define STAGEB  20480        // x2 stages = 40960B static smem

__device__ int g_cnt;
__device__ int g_list[40960];

// ---------- helpers ----------
__device__ __forceinline__ uint32_t smem_u32(const void* p) {
    uint32_t a;
    asm("{ .reg .u64 t; cvta.to.shared.u64 t, %1; cvt.u32.u64 %0, t; }" : "=r"(a) : "l"(p));
    return a;
}
__device__ __forceinline__ void sts128(uint32_t a, uint32_t x, uint32_t y, uint32_t z, uint32_t w) {
    asm volatile("st.shared.v4.b32 [%0], {%1,%2,%3,%4};" :: "r"(a), "r"(x), "r"(y), "r"(z), "r"(w) : "memory");
}
__device__ __forceinline__ void ldm4(uint32_t addr, uint32_t* r) {
    asm volatile("ldmatrix.sync.aligned.m8n8.x4.shared.b16 {%0,%1,%2,%3}, [%4];"
                 : "=r"(r[0]), "=r"(r[1]), "=r"(r[2]), "=r"(r[3]) : "r"(addr));
}
__device__ __forceinline__ void mma16(float* c, const uint32_t* a, uint32_t b0, uint32_t b1) {
    asm volatile(
        "mma.sync.aligned.m16n8k16.row.col.f32.bf16.bf16.f32 "
        "{%0,%1,%2,%3}, {%4,%5,%6,%7}, {%8,%9}, {%0,%1,%2,%3};"
        : "+f"(c[0]), "+f"(c[1]), "+f"(c[2]), "+f"(c[3])
        : "r"(a[0]), "r"(a[1]), "r"(a[2]), "r"(a[3]), "r"(b0), "r"(b1));
}
// split fp32 -> (hi bf16, lo bf16) pair packed as two uints per 4 values
__device__ __forceinline__ void split4(float4 v, uint32_t* hu, uint32_t* lu) {
    __nv_bfloat16 hx = __float2bfloat16_rn(v.x);
    __nv_bfloat16 hy = __float2bfloat16_rn(v.y);
    __nv_bfloat16 hz = __float2bfloat16_rn(v.z);
    __nv_bfloat16 hw = __float2bfloat16_rn(v.w);
    __nv_bfloat16 lx = __float2bfloat16_rn(v.x - __bfloat162float(hx));
    __nv_bfloat16 ly = __float2bfloat16_rn(v.y - __bfloat162float(hy));
    __nv_bfloat16 lz = __float2bfloat16_rn(v.z - __bfloat162float(hz));
    __nv_bfloat16 lw = __float2bfloat16_rn(v.w - __bfloat162float(hw));
    hu[0] = (uint32_t)__bfloat16_as_ushort(hx) | ((uint32_t)__bfloat16_as_ushort(hy) << 16);
    hu[1] = (uint32_t)__bfloat16_as_ushort(hz) | ((uint32_t)__bfloat16_as_ushort(hw) << 16);
    lu[0] = (uint32_t)__bfloat16_as_ushort(lx) | ((uint32_t)__bfloat16_as_ushort(ly) << 16);
    lu[1] = (uint32_t)__bfloat16_as_ushort(lz) | ((uint32_t)__bfloat16_as_ushort(lw) << 16);
}

struct Top3 { float v0, v1, v2; int i0, i1; };
__device__ __forceinline__ void t3_insert(Top3& t, float v, int i) {
    if (v > t.v0 || (v == t.v0 && i < t.i0)) {
        t.v2 = t.v1; t.v1 = t.v0; t.i1 = t.i0; t.v0 = v; t.i0 = i;
    } else if (v > t.v1 || (v == t.v1 && i < t.i1)) {
        t.v2 = t.v1; t.v1 = v; t.i1 = i;
    } else if (v > t.v2) {
        t.v2 = v;
    }
}
__device__ __forceinline__ void t3_merge_xor(Top3& t, int m) {
    float pv0 = __shfl_xor_sync(0xFFFFFFFFu, t.v0, m);
    float pv1 = __shfl_xor_sync(0xFFFFFFFFu, t.v1, m);
    float pv2 = __shfl_xor_sync(0xFFFFFFFFu, t.v2, m);
    int   pi0 = __shfl_xor_sync(0xFFFFFFFFu, t.i0, m);
    int   pi1 = __shfl_xor_sync(0xFFFFFFFFu, t.i1, m);
    t3_insert(t, pv0, pi0);
    t3_insert(t, pv1, pi1);
    t3_insert(t, pv2, 0x40000000);
}

// =========================================================================
// Main GEMM: emulated-fp32 via hi/lo-bf16 3-pass mma.sync.m16n8k16
// =========================================================================
__global__ __launch_bounds__(NT)
void router_mma(const float* __restrict__ x,
                const float* __restrict__ w,
                float* __restrict__ out_mask,
                float* __restrict__ out_w,
                float* __restrict__ out_i)
{
    __shared__ __align__(16) char smem[2 * STAGEB];
    const uint32_t smb = smem_u32(smem);

    const int tid  = threadIdx.x;
    const int lane = tid & 31;
    const int wid  = tid >> 5;       // 0..3
    const int gr   = lane >> 2;
    const int gc   = lane & 3;
    const int m0   = wid * 16;       // warp token base within tile
    const int mbase = blockIdx.x * BM;

    // ---- fill assignment: 64 rows x 2 halves for A and for B ----
    const int ar = tid >> 1;            // A row (token)
    const int ah_half = tid & 1;        // k-half (16 floats)
    const float4* xr = (const float4*)(x + (size_t)(mbase + ar) * DIMK + ah_half * 16);
    const float4* wr = (const float4*)(w + (size_t)ar * DIMK + ah_half * 16);
    const uint32_t a_sts = smb + OFF_AH + (uint32_t)(ar * ROWB + ah_half * 32);
    const uint32_t b_sts = smb + OFF_BH + (uint32_t)(ar * ROWB + ah_half * 32);

    // ---- ldmatrix lane addresses ----
    const uint32_t a_ld = smb + OFF_AH +
        (uint32_t)((m0 + ((lane >> 3) & 1) * 8 + (lane & 7)) * ROWB + (lane >> 4) * 16);
    const uint32_t b_ld_base = smb + OFF_BH +
        (uint32_t)((((lane >> 4) & 1) * 8 + (lane & 7)) * ROWB + ((lane >> 3) & 1) * 16);

    // ---- accumulators: 8 n-tiles x 4 regs ----
    float acc[8][4];
#pragma unroll
    for (int j = 0; j < 8; j++)
#pragma unroll
        for (int r = 0; r < 4; r++) acc[j][r] = 0.0f;

    // prefetch chunk 0 (4 float4 of x-row-half + 4 of w-row-half)
    float4 pa[4], pb[4];
#pragma unroll
    for (int q = 0; q < 4; q++) { pa[q] = xr[q]; pb[q] = wr[q]; }

#pragma unroll 1
    for (int c = 0; c < NCH; c++) {
        const uint32_t stg = (uint32_t)((c & 1) * STAGEB);
        if (c >= 2) __syncthreads();

        // ---- split & store (hi/lo bf16) ----
        uint32_t hu[8], lu[8];
#pragma unroll
        for (int q = 0; q < 4; q++) split4(pa[q], hu + 2 * q, lu + 2 * q);
        sts128(a_sts + stg,      hu[0], hu[1], hu[2], hu[3]);
        sts128(a_sts + stg + 16, hu[4], hu[5], hu[6], hu[7]);
        sts128(a_sts + stg + (OFF_AL - OFF_AH),      lu[0], lu[1], lu[2], lu[3]);
        sts128(a_sts + stg + (OFF_AL - OFF_AH) + 16, lu[4], lu[5], lu[6], lu[7]);
#pragma unroll
        for (int q = 0; q < 4; q++) split4(pb[q], hu + 2 * q, lu + 2 * q);
        sts128(b_sts + stg,      hu[0], hu[1], hu[2], hu[3]);
        sts128(b_sts + stg + 16, hu[4], hu[5], hu[6], hu[7]);
        sts128(b_sts + stg + (OFF_BL - OFF_BH),      lu[0], lu[1], lu[2], lu[3]);
        sts128(b_sts + stg + (OFF_BL - OFF_BH) + 16, lu[4], lu[5], lu[6], lu[7]);

        // ---- prefetch next chunk ----
        if (c + 1 < NCH) {
#pragma unroll
            for (int q = 0; q < 4; q++) {
                pa[q] = xr[(c + 1) * 8 + q];
                pb[q] = wr[(c + 1) * 8 + q];
            }
        }
        __syncthreads();

        // ---- compute: 2 k16-steps, 3 bf16 passes (hh, hl, lh) ----
#pragma unroll
        for (int ks = 0; ks < 2; ks++) {
            const uint32_t ko = stg + ks * 32;
            uint32_t ahf[4], alf[4];
            ldm4(a_ld + ko, ahf);
            ldm4(a_ld + ko + (OFF_AL - OFF_AH), alf);
            uint32_t bh[8][2], bl[8][2];
#pragma unroll
            for (int jp = 0; jp < 4; jp++) {
                uint32_t t4[4];
                uint32_t ba = b_ld_base + (uint32_t)(jp * 16 * ROWB) + ko;
                ldm4(ba, t4);
                bh[2 * jp][0] = t4[0]; bh[2 * jp][1] = t4[1];
                bh[2 * jp + 1][0] = t4[2]; bh[2 * jp + 1][1] = t4[3];
                ldm4(ba + (OFF_BL - OFF_BH), t4);
                bl[2 * jp][0] = t4[0]; bl[2 * jp][1] = t4[1];
                bl[2 * jp + 1][0] = t4[2]; bl[2 * jp + 1][1] = t4[3];
            }
#pragma unroll
            for (int j = 0; j < 8; j++) {
                mma16(acc[j], ahf, bh[j][0], bh[j][1]);   // hi*hi
                mma16(acc[j], ahf, bl[j][0], bl[j][1]);   // hi*lo
                mma16(acc[j], alf, bh[j][0], bh[j][1]);   // lo*hi
            }
        }
    }

    // =================== epilogue: top-2 per token ===================
#pragma unroll
    for (int rh = 0; rh < 2; rh++) {
        const int m = m0 + rh * 8 + gr;
        Top3 t; t.v0 = -1e30f; t.v1 = -1e30f; t.v2 = -1e30f; t.i0 = 0; t.i1 = 0;
#pragma unroll
        for (int j = 0; j < 8; j++) {
#pragma unroll
            for (int b = 0; b < 2; b++)
                t3_insert(t, acc[j][rh * 2 + b], 8 * j + 2 * gc + b);
        }
        t3_merge_xor(t, 1);
        t3_merge_xor(t, 2);

        const size_t g = (size_t)(mbase + m);
        if (gc == 0) {
            float e1  = expf(t.v1 - t.v0);
            float inv = 1.0f / (1.0f + e1);
            out_w[g * 2 + 0] = inv;
            out_w[g * 2 + 1] = e1 * inv;
            out_i[g * 2 + 0] = (float)t.i0;
            out_i[g * 2 + 1] = (float)t.i1;
            if ((t.v0 - t.v1 < DELTA) || (t.v1 - t.v2 < DELTA)) {
                int slot = atomicAdd(&g_cnt, 1);
                if (slot < 40960) g_list[slot] = (int)g;
            }
        }
        float* mrow = out_mask + g * NEXP + gc * 16;
#pragma unroll
        for (int q = 0; q < 4; q++) {
            int e0 = gc * 16 + q * 4;
            float4 mv;
            mv.x = (e0 + 0 == t.i0 || e0 + 0 == t.i1) ? 1.0f : 0.0f;
            mv.y = (e0 + 1 == t.i0 || e0 + 1 == t.i1) ? 1.0f : 0.0f;
            mv.z = (e0 + 2 == t.i0 || e0 + 2 == t.i1) ? 1.0f : 0.0f;
            mv.w = (e0 + 3 == t.i0 || e0 + 3 == t.i1) ? 1.0f : 0.0f;
            *(float4*)(mrow + q * 4) = mv;
        }
    }
}

// =========================================================================
// Repair: exact fp32 recompute of low-margin tokens (one warp per token)
// =========================================================================
__global__ __launch_bounds__(256)
void repair_kernel(const float* __restrict__ x,
                   const float* __restrict__ w,
                   float* __restrict__ out_mask,
                   float* __restrict__ out_w,
                   float* __restrict__ out_i)
{
    const int lane = threadIdx.x & 31;
    const int wgid = (blockIdx.x * blockDim.x + threadIdx.x) >> 5;
    const int nwarps = (gridDim.x * blockDim.x) >> 5;
    int cnt = g_cnt;
    if (cnt > 40960) cnt = 40960;

    for (int t = wgid; t < cnt; t += nwarps) {
        const int tok = g_list[t];
        const float4* xr = (const float4*)(x + (size_t)tok * DIMK);
        const float4* wa = (const float4*)(w + (size_t)lane * DIMK);
        const float4* wb = (const float4*)(w + (size_t)(lane + 32) * DIMK);

        float4 ma = make_float4(0, 0, 0, 0), mb = make_float4(0, 0, 0, 0);
#pragma unroll 1
        for (int seg = 0; seg < 8; seg++) {
            float4 ca = make_float4(0, 0, 0, 0), cb = make_float4(0, 0, 0, 0);
#pragma unroll 8
            for (int q = 0; q < 64; q++) {
                float4 xv = xr[seg * 64 + q];
                float4 va = wa[seg * 64 + q];
                float4 vb = wb[seg * 64 + q];
                ca.x = fmaf(xv.x, va.x, ca.x); ca.y = fmaf(xv.y, va.y, ca.y);
                ca.z = fmaf(xv.z, va.z, ca.z); ca.w = fmaf(xv.w, va.w, ca.w);
                cb.x = fmaf(xv.x, vb.x, cb.x); cb.y = fmaf(xv.y, vb.y, cb.y);
                cb.z = fmaf(xv.z, vb.z, cb.z); cb.w = fmaf(xv.w, vb.w, cb.w);
            }
            ma.x += ca.x; ma.y += ca.y; ma.z += ca.z; ma.w += ca.w;
            mb.x += cb.x; mb.y += cb.y; mb.z += cb.z; mb.w += cb.w;
        }
        float la = (ma.x + ma.y) + (ma.z + ma.w);
        float lb = (mb.x + mb.y) + (mb.z + mb.w);

        Top3 tp; tp.v0 = -1e30f; tp.v1 = -1e30f; tp.v2 = -1e30f; tp.i0 = 0; tp.i1 = 0;
        t3_insert(tp, la, lane);
        t3_insert(tp, lb, lane + 32);
        t3_merge_xor(tp, 1);
        t3_merge_xor(tp, 2);
        t3_merge_xor(tp, 4);
        t3_merge_xor(tp, 8);
        t3_merge_xor(tp, 16);

        if (lane == 0) {
            float e1  = expf(tp.v1 - tp.v0);
            float inv = 1.0f / (1.0f + e1);
            out_w[(size_t)tok * 2 + 0] = inv;
            out_w[(size_t)tok * 2 + 1] = e1 * inv;
            out_i[(size_t)tok * 2 + 0] = (float)tp.i0;
            out_i[(size_t)tok * 2 + 1] = (float)tp.i1;
        }
        __syncwarp();
        out_mask[(size_t)tok * NEXP + lane] =
            (lane == tp.i0 || lane == tp.i1) ? 1.0f : 0.0f;
        out_mask[(size_t)tok * NEXP + lane + 32] =
            (lane + 32 == tp.i0 || lane + 32 == tp.i1) ? 1.0f : 0.0f;
    }
}

extern "C" void kernel_launch(void* const* d_in, const int* in_sizes, int n_in,
                              void* d_out, int out_size) {
    const float* x = (const float*)d_in[0];   // (N, 2048) fp32
    const float* w = (const float*)d_in[1];   // (64, 2048) fp32
    int n_tokens = in_sizes[0] / DIMK;        // 32768

    float* out      = (float*)d_out;
    float* out_mask = out;                                  // N*64
    float* out_w    = out + (size_t)n_tokens * NEXP;        // N*2
    float* out_i    = out_w + (size_t)n_tokens * 2;         // N*2

    static void* cnt_addr = nullptr;
    if (!cnt_addr) cudaGetSymbolAddress(&cnt_addr, g_cnt);

    cudaMemsetAsync(cnt_addr, 0, sizeof(int));
    router_mma<<<n_tokens / BM, NT>>>(x, w, out_mask, out_w, out_i);
    repair_kernel<<<128, 256>>>(x, w, out_mask, out_w, out_i);
}